// round 8
// baseline (speedup 1.0000x reference)
#include <cuda_runtime.h>
#include <cstdint>
#include <cstddef>

namespace {
constexpr int Bn = 64, Sn = 512, In = 512, Hn = 1024, On = 512;
constexpr int COMBn = In + Hn;          // 1536
constexpr int NG = 128, NY = 16, NB = NG + NY;   // 144 CTAs
constexpr int NT = 256;
constexpr int RC = 8, NCH = Bn / RC;    // 8 rows per chunk, 8 chunks
constexpr int G_SLICE = COMBn / 8;      // 192 floats per k-slice
constexpr int G_SLP = G_SLICE + 4;      // 196 (bank skew)
constexpr int G_ROW = 8 * G_SLP;        // 1568 floats per A row
constexpr int Y_SLICE = Hn / 8;         // 128
constexpr int Y_SLP = Y_SLICE + 4;      // 132
constexpr int Y_ROW = 8 * Y_SLP;        // 1056
constexpr int P_LD = 65;                // padded preact leading dim
constexpr int SMEM_FLOATS = 2 * RC * G_ROW + 32 * P_LD;  // 27168
constexpr int SMEM_BYTES = SMEM_FLOATS * 4;              // 108672
}

__device__ float g_h[2 * Bn * Hn];           // h double buffer
__device__ unsigned g_count = 0;             // barrier arrivals
__device__ volatile unsigned g_gen = 0;      // barrier generation

__device__ __forceinline__ void cp16(unsigned dst, const float* src) {
    asm volatile("cp.async.cg.shared.global [%0], [%1], 16;" :: "r"(dst), "l"(src));
}
__device__ __forceinline__ void cp_commit() {
    asm volatile("cp.async.commit_group;" ::: "memory");
}
template <int N>
__device__ __forceinline__ void cp_wait() {
    asm volatile("cp.async.wait_group %0;" :: "n"(N) : "memory");
}

// Packed fp32 pair FMA (SASS FFMA2): acc.{lo,hi} += a.{lo,hi} * w.{lo,hi}
#define FMA2(acc, aa, ww) \
    asm("fma.rn.f32x2 %0, %1, %2, %0;" : "+l"(acc) : "l"(aa), "l"(ww))

__device__ __forceinline__ float psum(unsigned long long v) {
    return __uint_as_float((unsigned)v) + __uint_as_float((unsigned)(v >> 32));
}
__device__ __forceinline__ float sigm(float v) {
    return 1.0f / (1.0f + __expf(-v));
}

__device__ __forceinline__ void grid_barrier() {
    __syncthreads();
    if (threadIdx.x == 0) {
        __threadfence();                       // release h writes
        unsigned my = g_gen;                   // stable: round can't end before our add
        if (atomicAdd(&g_count, 1u) == (unsigned)(NB - 1)) {
            g_count = 0u;                      // reset before release (wrap-safe)
            __threadfence();
            g_gen = my + 1u;
        } else {
            while (g_gen == my) { }
            __threadfence();                   // acquire
        }
    }
    __syncthreads();
}

__global__ void __launch_bounds__(NT) lstm_fused(
    const float* __restrict__ x,  const float* __restrict__ h0, const float* __restrict__ c0,
    const float* __restrict__ Wf, const float* __restrict__ bf,
    const float* __restrict__ Wi, const float* __restrict__ bi,
    const float* __restrict__ Wc, const float* __restrict__ bc,
    const float* __restrict__ Wo, const float* __restrict__ bo,
    const float* __restrict__ Wy, const float* __restrict__ by,
    float* __restrict__ out)
{
    extern __shared__ float sm[];
    const int blk = blockIdx.x, t = threadIdx.x;
    float* yout = out;
    float* hout = out + (size_t)Bn * Sn * On;
    float* cout = hout + (size_t)Bn * Hn;

    if (blk < NG) {
        // ----------------- gate CTA: 8 hidden units, 32 preact cols -----------------
        float* sA = sm;
        float* sP = sm + 2 * RC * G_ROW;
        const int n0 = blk * 8;
        const int c  = t >> 3;                 // 0..31 (gate*8 + unit)
        const int sl = t & 7;                  // k-slice
        const int gg = c >> 3, dn = c & 7;
        const float* Wsel = (gg == 0) ? Wf : (gg == 1) ? Wi : (gg == 2) ? Wc : Wo;
        const unsigned long long* wp =
            (const unsigned long long*)(Wsel + (size_t)(n0 + dn) * COMBn + sl * G_SLICE);
        unsigned long long w[G_SLICE / 2];     // 96 pairs, stationary all run
#pragma unroll
        for (int j = 0; j < G_SLICE / 2; ++j) w[j] = wp[j];

        // cell-update ownership: (r = t>>2, units cd0, cd0+1) — coalesced h stores
        const int cr = t >> 2, cd0 = (t & 3) << 1, cd1 = cd0 + 1;
        float cell0 = c0[(size_t)cr * Hn + n0 + cd0];
        float cell1 = c0[(size_t)cr * Hn + n0 + cd1];
        const float bf0 = bf[n0 + cd0], bi0 = bi[n0 + cd0], bc0 = bc[n0 + cd0], bo0 = bo[n0 + cd0];
        const float bf1 = bf[n0 + cd1], bi1 = bi[n0 + cd1], bc1 = bc[n0 + cd1], bo1 = bo[n0 + cd1];

#pragma unroll 1
        for (int it = 0; it < Sn; ++it) {
            const float* hsrc = (it == 0) ? h0 : (g_h + (size_t)(it & 1) * (Bn * Hn));

            auto stage = [&](int ch, int bsel) {
                float* dstb = sA + bsel * (RC * G_ROW);
#pragma unroll 1
                for (int i = t; i < RC * (COMBn / 4); i += NT) {
                    int rl  = i / (COMBn / 4);
                    int kc  = i - rl * (COMBn / 4);
                    int ssl = kc / (G_SLICE / 4);
                    int off = kc - ssl * (G_SLICE / 4);
                    int k   = kc * 4;
                    int r   = ch * RC + rl;
                    const float* src = (k < In)
                        ? (x + ((size_t)r * Sn + it) * In + k)
                        : (hsrc + (size_t)r * Hn + (k - In));
                    float* dst = dstb + rl * G_ROW + ssl * G_SLP + off * 4;
                    cp16((unsigned)__cvta_generic_to_shared(dst), src);
                }
            };

            stage(0, 0);
            cp_commit();
#pragma unroll 1
            for (int ch = 0; ch < NCH; ++ch) {
                if (ch + 1 < NCH) { stage(ch + 1, (ch + 1) & 1); cp_commit(); cp_wait<1>(); }
                else              { cp_wait<0>(); }
                __syncthreads();
                const float* ab = sA + (ch & 1) * (RC * G_ROW) + sl * G_SLP;
#pragma unroll 1
                for (int rr = 0; rr < RC; ++rr) {
                    const ulonglong2* ap = (const ulonglong2*)(ab + rr * G_ROW);
                    unsigned long long a0 = 0, a1 = 0, a2 = 0, a3 = 0;
#pragma unroll
                    for (int j = 0; j < G_SLICE / 4; ++j) {   // 48 x LDS.128
                        ulonglong2 av = ap[j];
                        if (j & 1) { FMA2(a2, av.x, w[2 * j]); FMA2(a3, av.y, w[2 * j + 1]); }
                        else       { FMA2(a0, av.x, w[2 * j]); FMA2(a1, av.y, w[2 * j + 1]); }
                    }
                    float v = (psum(a0) + psum(a2)) + (psum(a1) + psum(a3));
                    v += __shfl_xor_sync(0xFFFFFFFFu, v, 1);
                    v += __shfl_xor_sync(0xFFFFFFFFu, v, 2);
                    v += __shfl_xor_sync(0xFFFFFFFFu, v, 4);
                    if (sl == 0) sP[c * P_LD + ch * RC + rr] = v;
                }
                __syncthreads();
            }

            // ---- combine: nonlinearity + cell/hidden update ----
            {
                float f0 = sigm(sP[(cd0     ) * P_LD + cr] + bf0);
                float i0 = sigm(sP[( 8 + cd0) * P_LD + cr] + bi0);
                float g0 = tanhf(sP[(16 + cd0) * P_LD + cr] + bc0);
                float o0 = sigm(sP[(24 + cd0) * P_LD + cr] + bo0);
                cell0 = f0 * cell0 + i0 * g0;
                float hh0 = o0 * tanhf(cell0);

                float f1 = sigm(sP[(cd1     ) * P_LD + cr] + bf1);
                float i1 = sigm(sP[( 8 + cd1) * P_LD + cr] + bi1);
                float g1 = tanhf(sP[(16 + cd1) * P_LD + cr] + bc1);
                float o1 = sigm(sP[(24 + cd1) * P_LD + cr] + bo1);
                cell1 = f1 * cell1 + i1 * g1;
                float hh1 = o1 * tanhf(cell1);

                float* hdst = g_h + (size_t)((it + 1) & 1) * (Bn * Hn) + (size_t)cr * Hn + n0;
                hdst[cd0] = hh0;
                hdst[cd1] = hh1;
                if (it == Sn - 1) {
                    hout[(size_t)cr * Hn + n0 + cd0] = hh0;
                    hout[(size_t)cr * Hn + n0 + cd1] = hh1;
                    cout[(size_t)cr * Hn + n0 + cd0] = cell0;
                    cout[(size_t)cr * Hn + n0 + cd1] = cell1;
                }
            }
            grid_barrier();
        }
    } else {
        // ----------------- y CTA: 32 output cols, one step behind -----------------
        float* sA = sm;
        const int cy0 = (blk - NG) * 32;
        const int c  = t >> 3;
        const int sl = t & 7;
        const unsigned long long* wp =
            (const unsigned long long*)(Wy + (size_t)(cy0 + c) * Hn + sl * Y_SLICE);
        unsigned long long w[Y_SLICE / 2];     // 64 pairs
#pragma unroll
        for (int j = 0; j < Y_SLICE / 2; ++j) w[j] = wp[j];
        const float bias = by[cy0 + c];

#pragma unroll 1
        for (int it = 0; it <= Sn; ++it) {
            if (it >= 1) {
                const float* hsrc = g_h + (size_t)(it & 1) * (Bn * Hn);  // h^{(it)}

                auto stage = [&](int ch, int bsel) {
                    float* dstb = sA + bsel * (RC * Y_ROW);
#pragma unroll 1
                    for (int i = t; i < RC * (Hn / 4); i += NT) {
                        int rl  = i / (Hn / 4);
                        int kc  = i - rl * (Hn / 4);
                        int ssl = kc / (Y_SLICE / 4);
                        int off = kc - ssl * (Y_SLICE / 4);
                        int r   = ch * RC + rl;
                        const float* src = hsrc + (size_t)r * Hn + kc * 4;
                        float* dst = dstb + rl * Y_ROW + ssl * Y_SLP + off * 4;
                        cp16((unsigned)__cvta_generic_to_shared(dst), src);
                    }
                };

                stage(0, 0);
                cp_commit();
#pragma unroll 1
                for (int ch = 0; ch < NCH; ++ch) {
                    if (ch + 1 < NCH) { stage(ch + 1, (ch + 1) & 1); cp_commit(); cp_wait<1>(); }
                    else              { cp_wait<0>(); }
                    __syncthreads();
                    const float* ab = sA + (ch & 1) * (RC * Y_ROW) + sl * Y_SLP;
#pragma unroll 1
                    for (int rr = 0; rr < RC; ++rr) {
                        const ulonglong2* ap = (const ulonglong2*)(ab + rr * Y_ROW);
                        unsigned long long a0 = 0, a1 = 0, a2 = 0, a3 = 0;
#pragma unroll
                        for (int j = 0; j < Y_SLICE / 4; ++j) {   // 32 x LDS.128
                            ulonglong2 av = ap[j];
                            if (j & 1) { FMA2(a2, av.x, w[2 * j]); FMA2(a3, av.y, w[2 * j + 1]); }
                            else       { FMA2(a0, av.x, w[2 * j]); FMA2(a1, av.y, w[2 * j + 1]); }
                        }
                        float v = (psum(a0) + psum(a2)) + (psum(a1) + psum(a3));
                        v += __shfl_xor_sync(0xFFFFFFFFu, v, 1);
                        v += __shfl_xor_sync(0xFFFFFFFFu, v, 2);
                        v += __shfl_xor_sync(0xFFFFFFFFu, v, 4);
                        if (sl == 0) {
                            int r = ch * RC + rr;
                            yout[((size_t)r * Sn + (it - 1)) * On + cy0 + c] = v + bias;
                        }
                    }
                    __syncthreads();
                }
            }
            if (it < Sn) grid_barrier();
        }
    }
}

extern "C" void kernel_launch(void* const* d_in, const int* in_sizes, int n_in,
                              void* d_out, int out_size) {
    (void)in_sizes; (void)n_in; (void)out_size;
    const float* x  = (const float*)d_in[0];
    const float* h0 = (const float*)d_in[1];
    const float* c0 = (const float*)d_in[2];
    const float* Wf = (const float*)d_in[3];
    const float* bf = (const float*)d_in[4];
    const float* Wi = (const float*)d_in[5];
    const float* bi = (const float*)d_in[6];
    const float* Wc = (const float*)d_in[7];
    const float* bc = (const float*)d_in[8];
    const float* Wo = (const float*)d_in[9];
    const float* bo = (const float*)d_in[10];
    const float* Wy = (const float*)d_in[11];
    const float* by = (const float*)d_in[12];
    float* out = (float*)d_out;

    cudaFuncSetAttribute(lstm_fused, cudaFuncAttributeMaxDynamicSharedMemorySize, SMEM_BYTES);
    lstm_fused<<<NB, NT, SMEM_BYTES>>>(x, h0, c0, Wf, bf, Wi, bi, Wc, bc, Wo, bo, Wy, by, out);
}

// round 9
// speedup vs baseline: 1.7332x; 1.7332x over previous
#include <cuda_runtime.h>
#include <cstdint>
#include <cstddef>

namespace {
constexpr int Bn = 64, Sn = 512, In = 512, Hn = 1024, On = 512;
constexpr int COMBn = In + Hn;          // 1536
constexpr int NG = 128, NY = 16, NB = NG + NY;   // 144 CTAs
constexpr int NT = 256;                 // 8 warps
constexpr int RC = 8, NCH = Bn / RC;    // 8 rows per staged chunk, 8 chunks
// gate A layout: per row, 32 slices x (48 + 4 pad) floats
constexpr int G_K   = 48;               // k floats per lane-slice
constexpr int G_SLP = G_K + 4;          // 52 (quad = (13*sl + j) mod 8, gcd(13,8)=1)
constexpr int G_ROW = 32 * G_SLP;       // 1664 floats per A row
// y A layout: per row, 32 slices x (32 + 4 pad) floats
constexpr int Y_K   = 32;
constexpr int Y_SLP = Y_K + 4;          // 36 (quad = (9*sl + j) mod 8)
constexpr int Y_ROW = 32 * Y_SLP;       // 1152
constexpr int P_LD = 65;                // padded preact leading dim
constexpr int SMEM_FLOATS = 2 * RC * G_ROW + 32 * P_LD;  // 26624 + 2080
constexpr int SMEM_BYTES = SMEM_FLOATS * 4;              // 114816
}

__device__ float g_h[2 * Bn * Hn];           // h double buffer
__device__ unsigned g_count = 0;             // barrier arrivals
__device__ volatile unsigned g_gen = 0;      // barrier generation

__device__ __forceinline__ void cp16(unsigned dst, const float* src) {
    asm volatile("cp.async.cg.shared.global [%0], [%1], 16;" :: "r"(dst), "l"(src));
}
__device__ __forceinline__ void cp_commit() {
    asm volatile("cp.async.commit_group;" ::: "memory");
}
template <int N>
__device__ __forceinline__ void cp_wait() {
    asm volatile("cp.async.wait_group %0;" :: "n"(N) : "memory");
}

// Packed fp32 pair FMA (SASS FFMA2): acc.{lo,hi} += a.{lo,hi} * w.{lo,hi}
#define FMA2(acc, aa, ww) \
    asm("fma.rn.f32x2 %0, %1, %2, %0;" : "+l"(acc) : "l"(aa), "l"(ww))

__device__ __forceinline__ float psum(unsigned long long v) {
    return __uint_as_float((unsigned)v) + __uint_as_float((unsigned)(v >> 32));
}
__device__ __forceinline__ float sigm(float v) {
    return 1.0f / (1.0f + __expf(-v));
}

__device__ __forceinline__ void grid_barrier() {
    __syncthreads();
    if (threadIdx.x == 0) {
        __threadfence();                       // release h writes
        unsigned my = g_gen;
        if (atomicAdd(&g_count, 1u) == (unsigned)(NB - 1)) {
            g_count = 0u;
            __threadfence();
            g_gen = my + 1u;
        } else {
            while (g_gen == my) { }
            __threadfence();                   // acquire
        }
    }
    __syncthreads();
}

// Reduce 4 independent values over 32 lanes in 6 shfls (value-routing butterfly).
// Result: lane groups of 8 hold full sums: lanes 0-7 -> v0, 8-15 -> v2,
// 16-23 -> v1, 24-31 -> v3.
__device__ __forceinline__ float reduce4(float v0, float v1, float v2, float v3, int lane) {
    bool hi16 = (lane & 16) != 0;
    float a  = hi16 ? v1 : v0;
    float ta = hi16 ? v0 : v1;
    a += __shfl_xor_sync(0xFFFFFFFFu, ta, 16);
    float b  = hi16 ? v3 : v2;
    float tb = hi16 ? v2 : v3;
    b += __shfl_xor_sync(0xFFFFFFFFu, tb, 16);
    bool hi8 = (lane & 8) != 0;
    float c  = hi8 ? b : a;
    float tc = hi8 ? a : b;
    c += __shfl_xor_sync(0xFFFFFFFFu, tc, 8);
    c += __shfl_xor_sync(0xFFFFFFFFu, c, 4);
    c += __shfl_xor_sync(0xFFFFFFFFu, c, 2);
    c += __shfl_xor_sync(0xFFFFFFFFu, c, 1);
    return c;
}

__global__ void __launch_bounds__(NT) lstm_fused(
    const float* __restrict__ x,  const float* __restrict__ h0, const float* __restrict__ c0,
    const float* __restrict__ Wf, const float* __restrict__ bf,
    const float* __restrict__ Wi, const float* __restrict__ bi,
    const float* __restrict__ Wc, const float* __restrict__ bc,
    const float* __restrict__ Wo, const float* __restrict__ bo,
    const float* __restrict__ Wy, const float* __restrict__ by,
    float* __restrict__ out)
{
    extern __shared__ float sm[];
    const int blk = blockIdx.x, t = threadIdx.x;
    const int wrp = t >> 5, lane = t & 31;
    float* yout = out;
    float* hout = out + (size_t)Bn * Sn * On;
    float* cout = hout + (size_t)Bn * Hn;

    // column owned by the reducing lane within a warp (lane%8 == 0 stores):
    // lane 0 -> base, lane 8 -> base+16, lane 16 -> base+8, lane 24 -> base+24
    const int redcol = ((lane & 8) ? 16 : 0) + ((lane & 16) ? 8 : 0);

    if (blk < NG) {
        // ------------- gate CTA: warp w owns unit n0+w across all 4 gates -------------
        float* sA = sm;
        float* sP = sm + 2 * RC * G_ROW;
        const int n0 = blk * 8;

        // Stationary weights: 4 cols x 48 k = 96 packed pairs
        unsigned long long wreg[96];
        {
            const float* g0 = Wf + (size_t)(n0 + wrp) * COMBn + lane * G_K;
            const float* g1 = Wi + (size_t)(n0 + wrp) * COMBn + lane * G_K;
            const float* g2 = Wc + (size_t)(n0 + wrp) * COMBn + lane * G_K;
            const float* g3 = Wo + (size_t)(n0 + wrp) * COMBn + lane * G_K;
#pragma unroll
            for (int j = 0; j < 24; ++j) {
                wreg[ 0 + j] = ((const unsigned long long*)g0)[j];
                wreg[24 + j] = ((const unsigned long long*)g1)[j];
                wreg[48 + j] = ((const unsigned long long*)g2)[j];
                wreg[72 + j] = ((const unsigned long long*)g3)[j];
            }
        }

        // cell-update ownership (combine phase): row cr, units cd0/cd1
        const int cr = t >> 2, cd0 = (t & 3) << 1, cd1 = cd0 + 1;
        float cell0 = c0[(size_t)cr * Hn + n0 + cd0];
        float cell1 = c0[(size_t)cr * Hn + n0 + cd1];
        const float bf0 = bf[n0 + cd0], bi0 = bi[n0 + cd0], bc0 = bc[n0 + cd0], bo0 = bo[n0 + cd0];
        const float bf1 = bf[n0 + cd1], bi1 = bi[n0 + cd1], bc1 = bc[n0 + cd1], bo1 = bo[n0 + cd1];

#pragma unroll 1
        for (int it = 0; it < Sn; ++it) {
            const float* hsrc = (it == 0) ? h0 : (g_h + (size_t)(it & 1) * (Bn * Hn));

            auto stage = [&](int ch, int bsel) {
                float* dstb = sA + bsel * (RC * G_ROW);
#pragma unroll 1
                for (int i = t; i < RC * (COMBn / 4); i += NT) {
                    int rl  = i / (COMBn / 4);
                    int kc  = i - rl * (COMBn / 4);
                    int ssl = kc / (G_K / 4);
                    int off = kc - ssl * (G_K / 4);
                    int k   = kc * 4;
                    int r   = ch * RC + rl;
                    const float* src = (k < In)
                        ? (x + ((size_t)r * Sn + it) * In + k)
                        : (hsrc + (size_t)r * Hn + (k - In));
                    float* dst = dstb + rl * G_ROW + ssl * G_SLP + off * 4;
                    cp16((unsigned)__cvta_generic_to_shared(dst), src);
                }
            };

            stage(0, 0);
            cp_commit();
#pragma unroll 1
            for (int ch = 0; ch < NCH; ++ch) {
                if (ch + 1 < NCH) { stage(ch + 1, (ch + 1) & 1); cp_commit(); cp_wait<1>(); }
                else              { cp_wait<0>(); }
                __syncthreads();
                const float* ab = sA + (ch & 1) * (RC * G_ROW) + lane * G_SLP;
#pragma unroll 1
                for (int rr = 0; rr < RC; ++rr) {
                    const ulonglong2* ap = (const ulonglong2*)(ab + rr * G_ROW);
                    unsigned long long a0 = 0, a1 = 0, a2 = 0, a3 = 0,
                                       a4 = 0, a5 = 0, a6 = 0, a7 = 0;
#pragma unroll
                    for (int j = 0; j < 12; ++j) {        // 12 LDS.128 -> 96 FMA2
                        ulonglong2 av = ap[j];
                        FMA2(a0, av.x, wreg[ 0 + 2 * j]); FMA2(a1, av.y, wreg[ 0 + 2 * j + 1]);
                        FMA2(a2, av.x, wreg[24 + 2 * j]); FMA2(a3, av.y, wreg[24 + 2 * j + 1]);
                        FMA2(a4, av.x, wreg[48 + 2 * j]); FMA2(a5, av.y, wreg[48 + 2 * j + 1]);
                        FMA2(a6, av.x, wreg[72 + 2 * j]); FMA2(a7, av.y, wreg[72 + 2 * j + 1]);
                    }
                    float v0 = psum(a0) + psum(a1);
                    float v1 = psum(a2) + psum(a3);
                    float v2 = psum(a4) + psum(a5);
                    float v3 = psum(a6) + psum(a7);
                    float red = reduce4(v0, v1, v2, v3, lane);
                    if ((lane & 7) == 0)
                        sP[(wrp + redcol) * P_LD + ch * RC + rr] = red;
                }
                __syncthreads();
            }

            // ---- combine: nonlinearity + cell/hidden update ----
            {
                float f0 = sigm(sP[(cd0     ) * P_LD + cr] + bf0);
                float i0 = sigm(sP[( 8 + cd0) * P_LD + cr] + bi0);
                float g0 = tanhf(sP[(16 + cd0) * P_LD + cr] + bc0);
                float o0 = sigm(sP[(24 + cd0) * P_LD + cr] + bo0);
                cell0 = f0 * cell0 + i0 * g0;
                float hh0 = o0 * tanhf(cell0);

                float f1 = sigm(sP[(cd1     ) * P_LD + cr] + bf1);
                float i1 = sigm(sP[( 8 + cd1) * P_LD + cr] + bi1);
                float g1 = tanhf(sP[(16 + cd1) * P_LD + cr] + bc1);
                float o1 = sigm(sP[(24 + cd1) * P_LD + cr] + bo1);
                cell1 = f1 * cell1 + i1 * g1;
                float hh1 = o1 * tanhf(cell1);

                float* hdst = g_h + (size_t)((it + 1) & 1) * (Bn * Hn) + (size_t)cr * Hn + n0;
                hdst[cd0] = hh0;
                hdst[cd1] = hh1;
                if (it == Sn - 1) {
                    hout[(size_t)cr * Hn + n0 + cd0] = hh0;
                    hout[(size_t)cr * Hn + n0 + cd1] = hh1;
                    cout[(size_t)cr * Hn + n0 + cd0] = cell0;
                    cout[(size_t)cr * Hn + n0 + cd1] = cell1;
                }
            }
            grid_barrier();
        }
    } else {
        // ------------- y CTA: warp w owns cols {cy0+w,+8,+16,+24}, one step behind -------------
        float* sA = sm;
        const int cy0 = (blk - NG) * 32;

        unsigned long long wreg[64];          // 4 cols x 32 k = 64 pairs
        {
            const float* y0 = Wy + (size_t)(cy0 + wrp     ) * Hn + lane * Y_K;
            const float* y1 = Wy + (size_t)(cy0 + wrp +  8) * Hn + lane * Y_K;
            const float* y2 = Wy + (size_t)(cy0 + wrp + 16) * Hn + lane * Y_K;
            const float* y3 = Wy + (size_t)(cy0 + wrp + 24) * Hn + lane * Y_K;
#pragma unroll
            for (int j = 0; j < 16; ++j) {
                wreg[ 0 + j] = ((const unsigned long long*)y0)[j];
                wreg[16 + j] = ((const unsigned long long*)y1)[j];
                wreg[32 + j] = ((const unsigned long long*)y2)[j];
                wreg[48 + j] = ((const unsigned long long*)y3)[j];
            }
        }
        const int mycol = cy0 + wrp + redcol;         // col stored by lanes lane%8==0
        const float bias = by[mycol];

#pragma unroll 1
        for (int it = 0; it <= Sn; ++it) {
            if (it >= 1) {
                const float* hsrc = g_h + (size_t)(it & 1) * (Bn * Hn);  // h^{(it)}

                auto stage = [&](int ch, int bsel) {
                    float* dstb = sA + bsel * (RC * Y_ROW);
#pragma unroll 1
                    for (int i = t; i < RC * (Hn / 4); i += NT) {
                        int rl  = i / (Hn / 4);
                        int kc  = i - rl * (Hn / 4);
                        int ssl = kc / (Y_K / 4);
                        int off = kc - ssl * (Y_K / 4);
                        int r   = ch * RC + rl;
                        const float* src = hsrc + (size_t)r * Hn + kc * 4;
                        float* dst = dstb + rl * Y_ROW + ssl * Y_SLP + off * 4;
                        cp16((unsigned)__cvta_generic_to_shared(dst), src);
                    }
                };

                stage(0, 0);
                cp_commit();
#pragma unroll 1
                for (int ch = 0; ch < NCH; ++ch) {
                    if (ch + 1 < NCH) { stage(ch + 1, (ch + 1) & 1); cp_commit(); cp_wait<1>(); }
                    else              { cp_wait<0>(); }
                    __syncthreads();
                    const float* ab = sA + (ch & 1) * (RC * Y_ROW) + lane * Y_SLP;
#pragma unroll 1
                    for (int rr = 0; rr < RC; ++rr) {
                        const ulonglong2* ap = (const ulonglong2*)(ab + rr * Y_ROW);
                        unsigned long long a0 = 0, a1 = 0, a2 = 0, a3 = 0,
                                           a4 = 0, a5 = 0, a6 = 0, a7 = 0;
#pragma unroll
                        for (int j = 0; j < 8; ++j) {     // 8 LDS.128 -> 64 FMA2
                            ulonglong2 av = ap[j];
                            FMA2(a0, av.x, wreg[ 0 + 2 * j]); FMA2(a1, av.y, wreg[ 0 + 2 * j + 1]);
                            FMA2(a2, av.x, wreg[16 + 2 * j]); FMA2(a3, av.y, wreg[16 + 2 * j + 1]);
                            FMA2(a4, av.x, wreg[32 + 2 * j]); FMA2(a5, av.y, wreg[32 + 2 * j + 1]);
                            FMA2(a6, av.x, wreg[48 + 2 * j]); FMA2(a7, av.y, wreg[48 + 2 * j + 1]);
                        }
                        float v0 = psum(a0) + psum(a1);
                        float v1 = psum(a2) + psum(a3);
                        float v2 = psum(a4) + psum(a5);
                        float v3 = psum(a6) + psum(a7);
                        float red = reduce4(v0, v1, v2, v3, lane);
                        if ((lane & 7) == 0) {
                            int r = ch * RC + rr;
                            yout[((size_t)r * Sn + (it - 1)) * On + mycol] = red + bias;
                        }
                    }
                    __syncthreads();
                }
            }
            if (it < Sn) grid_barrier();
        }
    }
}

extern "C" void kernel_launch(void* const* d_in, const int* in_sizes, int n_in,
                              void* d_out, int out_size) {
    (void)in_sizes; (void)n_in; (void)out_size;
    const float* x  = (const float*)d_in[0];
    const float* h0 = (const float*)d_in[1];
    const float* c0 = (const float*)d_in[2];
    const float* Wf = (const float*)d_in[3];
    const float* bf = (const float*)d_in[4];
    const float* Wi = (const float*)d_in[5];
    const float* bi = (const float*)d_in[6];
    const float* Wc = (const float*)d_in[7];
    const float* bc = (const float*)d_in[8];
    const float* Wo = (const float*)d_in[9];
    const float* bo = (const float*)d_in[10];
    const float* Wy = (const float*)d_in[11];
    const float* by = (const float*)d_in[12];
    float* out = (float*)d_out;

    cudaFuncSetAttribute(lstm_fused, cudaFuncAttributeMaxDynamicSharedMemorySize, SMEM_BYTES);
    lstm_fused<<<NB, NT, SMEM_BYTES>>>(x, h0, c0, Wf, bf, Wi, bi, Wc, bc, Wo, bo, Wy, by, out);
}

// round 10
// speedup vs baseline: 1.7790x; 1.0264x over previous
#include <cuda_runtime.h>
#include <cstdint>
#include <cstddef>

namespace {
constexpr int Bn = 64, Sn = 512, In = 512, Hn = 1024, On = 512;
constexpr int COMBn = In + Hn;          // 1536
constexpr int NG = 128, NY = 16, NB = NG + NY;   // 144 CTAs
constexpr int NT = 512;                 // 16 warps
constexpr int RC = 8, NCH = Bn / RC;    // 8 rows per staged chunk, 8 chunks
// gate A layout: per row, 64 slices x (24 + 4 pad) floats; phase = 7*sl+j mod 8 (gcd 1)
constexpr int G_K   = 24;
constexpr int G_SLP = G_K + 4;          // 28
constexpr int G_ROW = 64 * G_SLP;       // 1792 floats per A row
// y A layout: per row, 64 slices x (16 + 4 pad) floats; phase = 5*sl+j mod 8
constexpr int Y_K   = 16;
constexpr int Y_SLP = Y_K + 4;          // 20
constexpr int Y_ROW = 64 * Y_SLP;       // 1280
constexpr int P_LD = 65;
constexpr int SP_PLANE = 32 * P_LD;     // 2080 floats per k-half plane
constexpr int SMEM_FLOATS = 2 * RC * G_ROW + 2 * SP_PLANE;  // 28672 + 4160
constexpr int SMEM_BYTES = SMEM_FLOATS * 4;                 // 131328
}

__device__ float g_h[2 * Bn * Hn];           // h double buffer
__device__ unsigned g_count = 0;             // barrier arrivals
__device__ volatile unsigned g_gen = 0;      // barrier generation

__device__ __forceinline__ void cp16(unsigned dst, const float* src) {
    asm volatile("cp.async.cg.shared.global [%0], [%1], 16;" :: "r"(dst), "l"(src));
}
__device__ __forceinline__ void cp_commit() {
    asm volatile("cp.async.commit_group;" ::: "memory");
}
template <int N>
__device__ __forceinline__ void cp_wait() {
    asm volatile("cp.async.wait_group %0;" :: "n"(N) : "memory");
}

// Packed fp32 pair FMA (SASS FFMA2): acc.{lo,hi} += a.{lo,hi} * w.{lo,hi}
#define FMA2(acc, aa, ww) \
    asm("fma.rn.f32x2 %0, %1, %2, %0;" : "+l"(acc) : "l"(aa), "l"(ww))

__device__ __forceinline__ float psum(unsigned long long v) {
    return __uint_as_float((unsigned)v) + __uint_as_float((unsigned)(v >> 32));
}
__device__ __forceinline__ float sigm(float v) {
    return 1.0f / (1.0f + __expf(-v));
}

__device__ __forceinline__ void grid_barrier() {
    __syncthreads();
    if (threadIdx.x == 0) {
        __threadfence();                       // release h writes
        unsigned my = g_gen;
        if (atomicAdd(&g_count, 1u) == (unsigned)(NB - 1)) {
            g_count = 0u;
            __threadfence();
            g_gen = my + 1u;
        } else {
            while (g_gen == my) { }
            __threadfence();                   // acquire
        }
    }
    __syncthreads();
}

// Reduce 4 values over 32 lanes in 6 shfls. Lanes 0-7 -> v0, 8-15 -> v2,
// 16-23 -> v1, 24-31 -> v3.
__device__ __forceinline__ float reduce4(float v0, float v1, float v2, float v3, int lane) {
    bool hi16 = (lane & 16) != 0;
    float a  = hi16 ? v1 : v0;
    float ta = hi16 ? v0 : v1;
    a += __shfl_xor_sync(0xFFFFFFFFu, ta, 16);
    float b  = hi16 ? v3 : v2;
    float tb = hi16 ? v2 : v3;
    b += __shfl_xor_sync(0xFFFFFFFFu, tb, 16);
    bool hi8 = (lane & 8) != 0;
    float c  = hi8 ? b : a;
    float tc = hi8 ? a : b;
    c += __shfl_xor_sync(0xFFFFFFFFu, tc, 8);
    c += __shfl_xor_sync(0xFFFFFFFFu, c, 4);
    c += __shfl_xor_sync(0xFFFFFFFFu, c, 2);
    c += __shfl_xor_sync(0xFFFFFFFFu, c, 1);
    return c;
}

__global__ void __launch_bounds__(NT) lstm_fused(
    const float* __restrict__ x,  const float* __restrict__ h0, const float* __restrict__ c0,
    const float* __restrict__ Wf, const float* __restrict__ bf,
    const float* __restrict__ Wi, const float* __restrict__ bi,
    const float* __restrict__ Wc, const float* __restrict__ bc,
    const float* __restrict__ Wo, const float* __restrict__ bo,
    const float* __restrict__ Wy, const float* __restrict__ by,
    float* __restrict__ out)
{
    extern __shared__ float sm[];
    const int blk = blockIdx.x, t = threadIdx.x;
    const int wrp = t >> 5, lane = t & 31;
    float* yout = out;
    float* hout = out + (size_t)Bn * Sn * On;
    float* cout = hout + (size_t)Bn * Hn;

    // column offset owned by the reducing lane within a warp (lane%8==0 stores)
    const int redcol = ((lane & 8) ? 16 : 0) + ((lane & 16) ? 8 : 0);
    const int u  = wrp & 7;                // unit / col-group within CTA
    const int kh = wrp >> 3;               // k-half

    if (blk < NG) {
        // -------- gate CTA: warp (u,kh) -> unit n0+u, 4 gates, K-half kh --------
        float* sA = sm;
        float* sP = sm + 2 * RC * G_ROW;   // two k-half planes of 32 x P_LD
        const int n0 = blk * 8;

        // Stationary weights: 4 cols x 24 k = 48 packed pairs (96 regs)
        unsigned long long wreg[48];
        {
            const float* b0 = Wf + (size_t)(n0 + u) * COMBn + kh * 768 + lane * G_K;
            const float* b1 = Wi + (size_t)(n0 + u) * COMBn + kh * 768 + lane * G_K;
            const float* b2 = Wc + (size_t)(n0 + u) * COMBn + kh * 768 + lane * G_K;
            const float* b3 = Wo + (size_t)(n0 + u) * COMBn + kh * 768 + lane * G_K;
#pragma unroll
            for (int j = 0; j < 12; ++j) {
                wreg[ 0 + j] = ((const unsigned long long*)b0)[j];
                wreg[12 + j] = ((const unsigned long long*)b1)[j];
                wreg[24 + j] = ((const unsigned long long*)b2)[j];
                wreg[36 + j] = ((const unsigned long long*)b3)[j];
            }
        }

        // combine-phase ownership: one (row, unit) element per thread
        const int cr = t >> 3, d = t & 7;
        float cell = c0[(size_t)cr * Hn + n0 + d];
        const float vbf = bf[n0 + d], vbi = bi[n0 + d], vbc = bc[n0 + d], vbo = bo[n0 + d];

#pragma unroll 1
        for (int it = 0; it < Sn; ++it) {
            const float* hsrc = (it == 0) ? h0 : (g_h + (size_t)(it & 1) * (Bn * Hn));

            auto stage = [&](int ch, int bsel) {
                float* dstb = sA + bsel * (RC * G_ROW);
#pragma unroll 1
                for (int i = t; i < RC * (COMBn / 4); i += NT) {   // 6 per thread
                    int rl  = i / (COMBn / 4);
                    int kc  = i - rl * (COMBn / 4);
                    int ssl = kc / (G_K / 4);
                    int off = kc - ssl * (G_K / 4);
                    int k   = kc * 4;
                    int r   = ch * RC + rl;
                    const float* src = (k < In)
                        ? (x + ((size_t)r * Sn + it) * In + k)
                        : (hsrc + (size_t)r * Hn + (k - In));
                    float* dst = dstb + rl * G_ROW + ssl * G_SLP + off * 4;
                    cp16((unsigned)__cvta_generic_to_shared(dst), src);
                }
            };

            stage(0, 0);
            cp_commit();
#pragma unroll 1
            for (int ch = 0; ch < NCH; ++ch) {
                if (ch + 1 < NCH) { stage(ch + 1, (ch + 1) & 1); cp_commit(); cp_wait<1>(); }
                else              { cp_wait<0>(); }
                __syncthreads();
                const float* ab = sA + (ch & 1) * (RC * G_ROW) + (kh * 32 + lane) * G_SLP;
#pragma unroll 1
                for (int rr = 0; rr < RC; ++rr) {
                    const ulonglong2* ap = (const ulonglong2*)(ab + rr * G_ROW);
                    unsigned long long a0 = 0, a1 = 0, a2 = 0, a3 = 0;
#pragma unroll
                    for (int j = 0; j < 6; ++j) {        // 6 LDS.128 -> 48 FMA2
                        ulonglong2 av = ap[j];
                        FMA2(a0, av.x, wreg[ 0 + 2 * j]);
                        FMA2(a1, av.x, wreg[12 + 2 * j]);
                        FMA2(a2, av.x, wreg[24 + 2 * j]);
                        FMA2(a3, av.x, wreg[36 + 2 * j]);
                        FMA2(a0, av.y, wreg[ 1 + 2 * j]);
                        FMA2(a1, av.y, wreg[13 + 2 * j]);
                        FMA2(a2, av.y, wreg[25 + 2 * j]);
                        FMA2(a3, av.y, wreg[37 + 2 * j]);
                    }
                    float red = reduce4(psum(a0), psum(a1), psum(a2), psum(a3), lane);
                    if ((lane & 7) == 0)
                        sP[kh * SP_PLANE + (u + redcol) * P_LD + ch * RC + rr] = red;
                }
                __syncthreads();
            }

            // ---- combine: one (row, unit) per thread ----
            {
                float pf = sP[(d     ) * P_LD + cr] + sP[SP_PLANE + (d     ) * P_LD + cr];
                float pi = sP[( 8 + d) * P_LD + cr] + sP[SP_PLANE + ( 8 + d) * P_LD + cr];
                float pc = sP[(16 + d) * P_LD + cr] + sP[SP_PLANE + (16 + d) * P_LD + cr];
                float po = sP[(24 + d) * P_LD + cr] + sP[SP_PLANE + (24 + d) * P_LD + cr];
                float f = sigm(pf + vbf);
                float i = sigm(pi + vbi);
                float g = tanhf(pc + vbc);
                float o = sigm(po + vbo);
                cell = f * cell + i * g;
                float hh = o * tanhf(cell);
                g_h[(size_t)((it + 1) & 1) * (Bn * Hn) + (size_t)cr * Hn + n0 + d] = hh;
                if (it == Sn - 1) {
                    hout[(size_t)cr * Hn + n0 + d] = hh;
                    cout[(size_t)cr * Hn + n0 + d] = cell;
                }
            }
            grid_barrier();
        }
    } else {
        // -------- y CTA: warp (u,kh) -> cols {cy0+u,+8,+16,+24}, K-half kh; one step behind --------
        float* sA = sm;
        float* yP = sm + 2 * RC * Y_ROW;   // two k-half planes of 32 x P_LD
        const int cy0 = (blk - NG) * 32;

        unsigned long long wreg[32];       // 4 cols x 16 k = 32 pairs
        {
            const float* y0 = Wy + (size_t)(cy0 + u     ) * Hn + kh * 512 + lane * Y_K;
            const float* y1 = Wy + (size_t)(cy0 + u +  8) * Hn + kh * 512 + lane * Y_K;
            const float* y2 = Wy + (size_t)(cy0 + u + 16) * Hn + kh * 512 + lane * Y_K;
            const float* y3 = Wy + (size_t)(cy0 + u + 24) * Hn + kh * 512 + lane * Y_K;
#pragma unroll
            for (int j = 0; j < 8; ++j) {
                wreg[ 0 + j] = ((const unsigned long long*)y0)[j];
                wreg[ 8 + j] = ((const unsigned long long*)y1)[j];
                wreg[16 + j] = ((const unsigned long long*)y2)[j];
                wreg[24 + j] = ((const unsigned long long*)y3)[j];
            }
        }

#pragma unroll 1
        for (int it = 0; it <= Sn; ++it) {
            if (it >= 1) {
                const float* hsrc = g_h + (size_t)(it & 1) * (Bn * Hn);  // h^{(it)}

                auto stage = [&](int ch, int bsel) {
                    float* dstb = sA + bsel * (RC * Y_ROW);
#pragma unroll 1
                    for (int i = t; i < RC * (Hn / 4); i += NT) {   // 4 per thread
                        int rl  = i / (Hn / 4);
                        int kc  = i - rl * (Hn / 4);
                        int ssl = kc / (Y_K / 4);
                        int off = kc - ssl * (Y_K / 4);
                        int r   = ch * RC + rl;
                        const float* src = hsrc + (size_t)r * Hn + kc * 4;
                        float* dst = dstb + rl * Y_ROW + ssl * Y_SLP + off * 4;
                        cp16((unsigned)__cvta_generic_to_shared(dst), src);
                    }
                };

                stage(0, 0);
                cp_commit();
#pragma unroll 1
                for (int ch = 0; ch < NCH; ++ch) {
                    if (ch + 1 < NCH) { stage(ch + 1, (ch + 1) & 1); cp_commit(); cp_wait<1>(); }
                    else              { cp_wait<0>(); }
                    __syncthreads();
                    const float* ab = sA + (ch & 1) * (RC * Y_ROW) + (kh * 32 + lane) * Y_SLP;
#pragma unroll 1
                    for (int rr = 0; rr < RC; ++rr) {
                        const ulonglong2* ap = (const ulonglong2*)(ab + rr * Y_ROW);
                        unsigned long long a0 = 0, a1 = 0, a2 = 0, a3 = 0;
#pragma unroll
                        for (int j = 0; j < 4; ++j) {     // 4 LDS.128 -> 32 FMA2
                            ulonglong2 av = ap[j];
                            FMA2(a0, av.x, wreg[ 0 + 2 * j]);
                            FMA2(a1, av.x, wreg[ 8 + 2 * j]);
                            FMA2(a2, av.x, wreg[16 + 2 * j]);
                            FMA2(a3, av.x, wreg[24 + 2 * j]);
                            FMA2(a0, av.y, wreg[ 1 + 2 * j]);
                            FMA2(a1, av.y, wreg[ 9 + 2 * j]);
                            FMA2(a2, av.y, wreg[17 + 2 * j]);
                            FMA2(a3, av.y, wreg[25 + 2 * j]);
                        }
                        float red = reduce4(psum(a0), psum(a1), psum(a2), psum(a3), lane);
                        if ((lane & 7) == 0)
                            yP[kh * SP_PLANE + (u + redcol) * P_LD + ch * RC + rr] = red;
                    }
                    __syncthreads();
                }

                // ---- combine halves + bias, store y_{it-1} ----
#pragma unroll 1
                for (int q = t; q < Bn * 32; q += NT) {   // 4 per thread
                    int r = q >> 5, col = q & 31;
                    float v = yP[col * P_LD + r] + yP[SP_PLANE + col * P_LD + r] + by[cy0 + col];
                    yout[((size_t)r * Sn + (it - 1)) * On + cy0 + col] = v;
                }
            }
            if (it < Sn) grid_barrier();
        }
    }
}

extern "C" void kernel_launch(void* const* d_in, const int* in_sizes, int n_in,
                              void* d_out, int out_size) {
    (void)in_sizes; (void)n_in; (void)out_size;
    const float* x  = (const float*)d_in[0];
    const float* h0 = (const float*)d_in[1];
    const float* c0 = (const float*)d_in[2];
    const float* Wf = (const float*)d_in[3];
    const float* bf = (const float*)d_in[4];
    const float* Wi = (const float*)d_in[5];
    const float* bi = (const float*)d_in[6];
    const float* Wc = (const float*)d_in[7];
    const float* bc = (const float*)d_in[8];
    const float* Wo = (const float*)d_in[9];
    const float* bo = (const float*)d_in[10];
    const float* Wy = (const float*)d_in[11];
    const float* by = (const float*)d_in[12];
    float* out = (float*)d_out;

    cudaFuncSetAttribute(lstm_fused, cudaFuncAttributeMaxDynamicSharedMemorySize, SMEM_BYTES);
    lstm_fused<<<NB, NT, SMEM_BYTES>>>(x, h0, c0, Wf, bf, Wi, bi, Wc, bc, Wo, bo, Wy, by, out);
}

// round 11
// speedup vs baseline: 1.8093x; 1.0171x over previous
#include <cuda_runtime.h>
#include <cstdint>
#include <cstddef>

namespace {
constexpr int Bn = 64, Sn = 512, In = 512, Hn = 1024, On = 512;
constexpr int COMBn = In + Hn;          // 1536
constexpr int NG = 128, NY = 16, NB = NG + NY;   // 144 CTAs
constexpr int NT = 512;                 // 16 warps
constexpr int RC = 8, NCH = Bn / RC;    // 8 rows per staged chunk, 8 chunks
// gate A layout: per row, 64 slices x (24 + 4 pad) floats; quad phase = 7*sl+j mod 8
constexpr int G_K   = 24;
constexpr int G_SLP = G_K + 4;          // 28
constexpr int G_ROW = 64 * G_SLP;       // 1792 floats per A row
// y A layout: per row, 64 slices x (16 + 4 pad) floats; quad phase = 5*sl+j mod 8
constexpr int Y_K   = 16;
constexpr int Y_SLP = Y_K + 4;          // 20
constexpr int Y_ROW = 64 * Y_SLP;       // 1280
constexpr int P_LD = 65;
constexpr int SP_PLANE = 32 * P_LD;     // 2080 floats per k-half plane
constexpr int SMEM_FLOATS = 2 * RC * G_ROW + 2 * SP_PLANE;  // 28672 + 4160
constexpr int SMEM_BYTES = SMEM_FLOATS * 4;                 // 131328
}

__device__ float g_h[2 * Bn * Hn];           // h double buffer
__device__ unsigned g_count = 0;             // barrier arrivals
__device__ volatile unsigned g_gen = 0;      // barrier generation

__device__ __forceinline__ void cp16(unsigned dst, const float* src) {
    asm volatile("cp.async.cg.shared.global [%0], [%1], 16;" :: "r"(dst), "l"(src));
}
__device__ __forceinline__ void cp_commit() {
    asm volatile("cp.async.commit_group;" ::: "memory");
}
template <int N>
__device__ __forceinline__ void cp_wait() {
    asm volatile("cp.async.wait_group %0;" :: "n"(N) : "memory");
}

// Packed fp32 pair FMA (SASS FFMA2): acc.{lo,hi} += a.{lo,hi} * w.{lo,hi}
#define FMA2(acc, aa, ww) \
    asm("fma.rn.f32x2 %0, %1, %2, %0;" : "+l"(acc) : "l"(aa), "l"(ww))

__device__ __forceinline__ float psum(unsigned long long v) {
    return __uint_as_float((unsigned)v) + __uint_as_float((unsigned)(v >> 32));
}
__device__ __forceinline__ float sigm(float v) {
    return 1.0f / (1.0f + __expf(-v));
}

__device__ __forceinline__ void grid_barrier() {
    __syncthreads();
    if (threadIdx.x == 0) {
        __threadfence();                       // release h writes
        unsigned my = g_gen;
        if (atomicAdd(&g_count, 1u) == (unsigned)(NB - 1)) {
            g_count = 0u;
            __threadfence();
            g_gen = my + 1u;
        } else {
            while (g_gen == my) { }
            __threadfence();                   // acquire
        }
    }
    __syncthreads();
}

// Reduce 4 values over 32 lanes in 6 shfls. Lanes 0-7 -> v0, 8-15 -> v2,
// 16-23 -> v1, 24-31 -> v3.
__device__ __forceinline__ float reduce4(float v0, float v1, float v2, float v3, int lane) {
    bool hi16 = (lane & 16) != 0;
    float a  = hi16 ? v1 : v0;
    float ta = hi16 ? v0 : v1;
    a += __shfl_xor_sync(0xFFFFFFFFu, ta, 16);
    float b  = hi16 ? v3 : v2;
    float tb = hi16 ? v2 : v3;
    b += __shfl_xor_sync(0xFFFFFFFFu, tb, 16);
    bool hi8 = (lane & 8) != 0;
    float c  = hi8 ? b : a;
    float tc = hi8 ? a : b;
    c += __shfl_xor_sync(0xFFFFFFFFu, tc, 8);
    c += __shfl_xor_sync(0xFFFFFFFFu, c, 4);
    c += __shfl_xor_sync(0xFFFFFFFFu, c, 2);
    c += __shfl_xor_sync(0xFFFFFFFFu, c, 1);
    return c;
}

__global__ void __launch_bounds__(NT) lstm_fused(
    const float* __restrict__ x,  const float* __restrict__ h0, const float* __restrict__ c0,
    const float* __restrict__ Wf, const float* __restrict__ bf,
    const float* __restrict__ Wi, const float* __restrict__ bi,
    const float* __restrict__ Wc, const float* __restrict__ bc,
    const float* __restrict__ Wo, const float* __restrict__ bo,
    const float* __restrict__ Wy, const float* __restrict__ by,
    float* __restrict__ out)
{
    extern __shared__ float sm[];
    const int blk = blockIdx.x, t = threadIdx.x;
    const int wrp = t >> 5, lane = t & 31;
    float* yout = out;
    float* hout = out + (size_t)Bn * Sn * On;
    float* cout = hout + (size_t)Bn * Hn;

    // column offset owned by the reducing lane within a warp (lane%8==0 stores)
    const int redcol = ((lane & 8) ? 16 : 0) + ((lane & 16) ? 8 : 0);
    const int u  = wrp & 7;                // unit / col-group within CTA
    const int kh = wrp >> 3;               // k-half
    // per-warp row-phase stagger; distinct among the 4 warps of each SMSP
    const int stag = (2 * (wrp & 3) + (wrp >> 2)) & 7;

    if (blk < NG) {
        // -------- gate CTA: warp (u,kh) -> unit n0+u, 4 gates, K-half kh --------
        float* sA = sm;
        float* sP = sm + 2 * RC * G_ROW;   // two k-half planes of 32 x P_LD
        const int n0 = blk * 8;

        // Stationary weights: 4 cols x 24 k = 48 packed pairs (96 regs)
        unsigned long long wreg[48];
        {
            const float* b0 = Wf + (size_t)(n0 + u) * COMBn + kh * 768 + lane * G_K;
            const float* b1 = Wi + (size_t)(n0 + u) * COMBn + kh * 768 + lane * G_K;
            const float* b2 = Wc + (size_t)(n0 + u) * COMBn + kh * 768 + lane * G_K;
            const float* b3 = Wo + (size_t)(n0 + u) * COMBn + kh * 768 + lane * G_K;
#pragma unroll
            for (int j = 0; j < 12; ++j) {
                wreg[ 0 + j] = ((const unsigned long long*)b0)[j];
                wreg[12 + j] = ((const unsigned long long*)b1)[j];
                wreg[24 + j] = ((const unsigned long long*)b2)[j];
                wreg[36 + j] = ((const unsigned long long*)b3)[j];
            }
        }

        // combine-phase ownership: one (row, unit) element per thread
        const int cr = t >> 3, d = t & 7;
        float cell = c0[(size_t)cr * Hn + n0 + d];
        const float vbf = bf[n0 + d], vbi = bi[n0 + d], vbc = bc[n0 + d], vbo = bo[n0 + d];

#pragma unroll 1
        for (int it = 0; it < Sn; ++it) {
            const float* hsrc = (it == 0) ? h0 : (g_h + (size_t)(it & 1) * (Bn * Hn));

            auto stage = [&](int ch, int bsel) {
                float* dstb = sA + bsel * (RC * G_ROW);
#pragma unroll 1
                for (int i = t; i < RC * (COMBn / 4); i += NT) {   // 6 per thread
                    int rl  = i / (COMBn / 4);
                    int kc  = i - rl * (COMBn / 4);
                    int ssl = kc / (G_K / 4);
                    int off = kc - ssl * (G_K / 4);
                    int k   = kc * 4;
                    int r   = ch * RC + rl;
                    const float* src = (k < In)
                        ? (x + ((size_t)r * Sn + it) * In + k)
                        : (hsrc + (size_t)r * Hn + (k - In));
                    float* dst = dstb + rl * G_ROW + ssl * G_SLP + off * 4;
                    cp16((unsigned)__cvta_generic_to_shared(dst), src);
                }
            };

            stage(0, 0);
            cp_commit();
#pragma unroll 1
            for (int ch = 0; ch < NCH; ++ch) {
                cp_wait<0>();
                __syncthreads();               // single sync: data of ch ready AND
                                               // all warps done consuming ch-1
                if (ch + 1 < NCH) { stage(ch + 1, (ch + 1) & 1); cp_commit(); }
                const float* ab = sA + (ch & 1) * (RC * G_ROW) + (kh * 32 + lane) * G_SLP;
#pragma unroll 1
                for (int rq = 0; rq < RC; ++rq) {
                    int rr = (rq + stag) & 7;  // per-warp staggered row order
                    const ulonglong2* ap = (const ulonglong2*)(ab + rr * G_ROW);
                    unsigned long long a0 = 0, a1 = 0, a2 = 0, a3 = 0;
#pragma unroll
                    for (int j = 0; j < 6; ++j) {        // 6 LDS.128 -> 48 FMA2
                        ulonglong2 av = ap[j];
                        FMA2(a0, av.x, wreg[ 0 + 2 * j]);
                        FMA2(a1, av.x, wreg[12 + 2 * j]);
                        FMA2(a2, av.x, wreg[24 + 2 * j]);
                        FMA2(a3, av.x, wreg[36 + 2 * j]);
                        FMA2(a0, av.y, wreg[ 1 + 2 * j]);
                        FMA2(a1, av.y, wreg[13 + 2 * j]);
                        FMA2(a2, av.y, wreg[25 + 2 * j]);
                        FMA2(a3, av.y, wreg[37 + 2 * j]);
                    }
                    float red = reduce4(psum(a0), psum(a1), psum(a2), psum(a3), lane);
                    if ((lane & 7) == 0)
                        sP[kh * SP_PLANE + (u + redcol) * P_LD + ch * RC + rr] = red;
                }
            }
            __syncthreads();                   // all sP writes visible for combine

            // ---- combine: one (row, unit) per thread ----
            {
                float pf = sP[(d     ) * P_LD + cr] + sP[SP_PLANE + (d     ) * P_LD + cr];
                float pi = sP[( 8 + d) * P_LD + cr] + sP[SP_PLANE + ( 8 + d) * P_LD + cr];
                float pc = sP[(16 + d) * P_LD + cr] + sP[SP_PLANE + (16 + d) * P_LD + cr];
                float po = sP[(24 + d) * P_LD + cr] + sP[SP_PLANE + (24 + d) * P_LD + cr];
                float f = sigm(pf + vbf);
                float i = sigm(pi + vbi);
                float g = tanhf(pc + vbc);
                float o = sigm(po + vbo);
                cell = f * cell + i * g;
                float hh = o * tanhf(cell);
                g_h[(size_t)((it + 1) & 1) * (Bn * Hn) + (size_t)cr * Hn + n0 + d] = hh;
                if (it == Sn - 1) {
                    hout[(size_t)cr * Hn + n0 + d] = hh;
                    cout[(size_t)cr * Hn + n0 + d] = cell;
                }
            }
            grid_barrier();
        }
    } else {
        // -------- y CTA: warp (u,kh) -> cols {cy0+u,+8,+16,+24}, K-half kh; one step behind --------
        float* sA = sm;
        float* yP = sm + 2 * RC * Y_ROW;   // two k-half planes of 32 x P_LD
        const int cy0 = (blk - NG) * 32;

        unsigned long long wreg[32];       // 4 cols x 16 k = 32 pairs
        {
            const float* y0 = Wy + (size_t)(cy0 + u     ) * Hn + kh * 512 + lane * Y_K;
            const float* y1 = Wy + (size_t)(cy0 + u +  8) * Hn + kh * 512 + lane * Y_K;
            const float* y2 = Wy + (size_t)(cy0 + u + 16) * Hn + kh * 512 + lane * Y_K;
            const float* y3 = Wy + (size_t)(cy0 + u + 24) * Hn + kh * 512 + lane * Y_K;
#pragma unroll
            for (int j = 0; j < 8; ++j) {
                wreg[ 0 + j] = ((const unsigned long long*)y0)[j];
                wreg[ 8 + j] = ((const unsigned long long*)y1)[j];
                wreg[16 + j] = ((const unsigned long long*)y2)[j];
                wreg[24 + j] = ((const unsigned long long*)y3)[j];
            }
        }

#pragma unroll 1
        for (int it = 0; it <= Sn; ++it) {
            if (it >= 1) {
                const float* hsrc = g_h + (size_t)(it & 1) * (Bn * Hn);  // h^{(it)}

                auto stage = [&](int ch, int bsel) {
                    float* dstb = sA + bsel * (RC * Y_ROW);
#pragma unroll 1
                    for (int i = t; i < RC * (Hn / 4); i += NT) {   // 4 per thread
                        int rl  = i / (Hn / 4);
                        int kc  = i - rl * (Hn / 4);
                        int ssl = kc / (Y_K / 4);
                        int off = kc - ssl * (Y_K / 4);
                        int r   = ch * RC + rl;
                        const float* src = hsrc + (size_t)r * Hn + kc * 4;
                        float* dst = dstb + rl * Y_ROW + ssl * Y_SLP + off * 4;
                        cp16((unsigned)__cvta_generic_to_shared(dst), src);
                    }
                };

                stage(0, 0);
                cp_commit();
#pragma unroll 1
                for (int ch = 0; ch < NCH; ++ch) {
                    cp_wait<0>();
                    __syncthreads();
                    if (ch + 1 < NCH) { stage(ch + 1, (ch + 1) & 1); cp_commit(); }
                    const float* ab = sA + (ch & 1) * (RC * Y_ROW) + (kh * 32 + lane) * Y_SLP;
#pragma unroll 1
                    for (int rq = 0; rq < RC; ++rq) {
                        int rr = (rq + stag) & 7;
                        const ulonglong2* ap = (const ulonglong2*)(ab + rr * Y_ROW);
                        unsigned long long a0 = 0, a1 = 0, a2 = 0, a3 = 0;
#pragma unroll
                        for (int j = 0; j < 4; ++j) {     // 4 LDS.128 -> 32 FMA2
                            ulonglong2 av = ap[j];
                            FMA2(a0, av.x, wreg[ 0 + 2 * j]);
                            FMA2(a1, av.x, wreg[ 8 + 2 * j]);
                            FMA2(a2, av.x, wreg[16 + 2 * j]);
                            FMA2(a3, av.x, wreg[24 + 2 * j]);
                            FMA2(a0, av.y, wreg[ 1 + 2 * j]);
                            FMA2(a1, av.y, wreg[ 9 + 2 * j]);
                            FMA2(a2, av.y, wreg[17 + 2 * j]);
                            FMA2(a3, av.y, wreg[25 + 2 * j]);
                        }
                        float red = reduce4(psum(a0), psum(a1), psum(a2), psum(a3), lane);
                        if ((lane & 7) == 0)
                            yP[kh * SP_PLANE + (u + redcol) * P_LD + ch * RC + rr] = red;
                    }
                }
                __syncthreads();               // all yP writes visible

                // ---- combine halves + bias, store y_{it-1} ----
#pragma unroll 1
                for (int q = t; q < Bn * 32; q += NT) {   // 4 per thread
                    int r = q >> 5, col = q & 31;
                    float v = yP[col * P_LD + r] + yP[SP_PLANE + col * P_LD + r] + by[cy0 + col];
                    yout[((size_t)r * Sn + (it - 1)) * On + cy0 + col] = v;
                }
            }
            if (it < Sn) grid_barrier();
        }
    }
}

extern "C" void kernel_launch(void* const* d_in, const int* in_sizes, int n_in,
                              void* d_out, int out_size) {
    (void)in_sizes; (void)n_in; (void)out_size;
    const float* x  = (const float*)d_in[0];
    const float* h0 = (const float*)d_in[1];
    const float* c0 = (const float*)d_in[2];
    const float* Wf = (const float*)d_in[3];
    const float* bf = (const float*)d_in[4];
    const float* Wi = (const float*)d_in[5];
    const float* bi = (const float*)d_in[6];
    const float* Wc = (const float*)d_in[7];
    const float* bc = (const float*)d_in[8];
    const float* Wo = (const float*)d_in[9];
    const float* bo = (const float*)d_in[10];
    const float* Wy = (const float*)d_in[11];
    const float* by = (const float*)d_in[12];
    float* out = (float*)d_out;

    cudaFuncSetAttribute(lstm_fused, cudaFuncAttributeMaxDynamicSharedMemorySize, SMEM_BYTES);
    lstm_fused<<<NB, NT, SMEM_BYTES>>>(x, h0, c0, Wf, bf, Wi, bi, Wc, bc, Wo, bo, Wy, by, out);
}